// round 13
// baseline (speedup 1.0000x reference)
#include <cuda_runtime.h>
#include <cuda_bf16.h>
#include <cstdint>

#define N_ 128
#define C_ 81
#define A_ 8732
#define A4_ 2183          // A_/4 exactly
#define A4P 3072          // padded uint4 groups (3 * 1024)
#define NB 4096
#define PCAP 2048         // per-row positive-index capacity (pos ~437)
#define DYN_BYTES ((A4P * 4 + 4 * NB) * 4)   // s_con + 4 hist replicas = 114688 B

// Scratch (device globals — no allocations allowed)
__device__ unsigned g_con[N_ * A_];
__device__ float    g_partcon[N_ * 16];
__device__ int      g_partpos[N_ * 16];
__device__ int      g_posidx[N_ * PCAP];   // compacted positive anchor indices
__device__ unsigned g_poscnt[N_];          // append counters (kT resets -> replay-safe)
__device__ float    g_row[N_];
__device__ unsigned g_count;               // self-resetting

// ---------------------------------------------------------------------------
// Kernel A: focal loss per anchor + positive-index compaction.
// grid = (9, N), block = 256. Whole block exits when domain_label != 0.
// ---------------------------------------------------------------------------
__global__ __launch_bounds__(256, 8) void kA_focal(const float* __restrict__ plabel,
                                                   const int*   __restrict__ glabel,
                                                   const int*   __restrict__ domain_label)
{
    const int n = blockIdx.y;
    if (domain_label[n] != 0) return;

    int idx = blockIdx.x * 256 + threadIdx.x;
    bool valid = (idx < A4_);
    int ii = valid ? idx : (A4_ - 1);

    const float4* P = (const float4*)(plabel + (size_t)n * C_ * A_) + ii;
    int4 g = ((const int4*)(glabel + (size_t)n * A_))[ii];

    float4 s  = make_float4(0.f, 0.f, 0.f, 0.f);
    float4 xg = make_float4(0.f, 0.f, 0.f, 0.f);
#pragma unroll 3
    for (int c = 0; c < C_; c++) {
        float4 x = __ldcs(P);
        P += A4_;
        if (c == g.x) xg.x = x.x;
        if (c == g.y) xg.y = x.y;
        if (c == g.z) xg.z = x.z;
        if (c == g.w) xg.w = x.w;
        s.x += __expf(x.x); s.y += __expf(x.y);
        s.z += __expf(x.z); s.w += __expf(x.w);
    }

    float lp0 = xg.x - __logf(s.x), lp1 = xg.y - __logf(s.y);
    float lp2 = xg.z - __logf(s.z), lp3 = xg.w - __logf(s.w);
    float o0 = 1.f - __expf(lp0), o1 = 1.f - __expf(lp1);
    float o2 = 1.f - __expf(lp2), o3 = 1.f - __expf(lp3);
    float c0 = -0.25f * o0 * o0 * lp0;
    float c1 = -0.25f * o1 * o1 * lp1;
    float c2 = -0.25f * o2 * o2 * lp2;
    float c3 = -0.25f * o3 * o3 * lp3;

    bool m0 = g.x > 0, m1 = g.y > 0, m2 = g.z > 0, m3 = g.w > 0;

    uint4 cw;
    cw.x = m0 ? 0u : __float_as_uint(c0);
    cw.y = m1 ? 0u : __float_as_uint(c1);
    cw.z = m2 ? 0u : __float_as_uint(c2);
    cw.w = m3 ? 0u : __float_as_uint(c3);
    ((uint4*)g_con)[(size_t)n * A4_ + ii] = cw;

    float contrib = 0.f;
    int pc = 0;
    if (valid) {
        if (m0) { contrib += c0; pc++; }
        if (m1) { contrib += c1; pc++; }
        if (m2) { contrib += c2; pc++; }
        if (m3) { contrib += c3; pc++; }
        // append positive anchor indices (compaction for kT's loc gather)
        if (pc) {
            unsigned p = atomicAdd(&g_poscnt[n], (unsigned)pc);
            int base = 4 * ii;
            if (m0 && p < PCAP) g_posidx[n * PCAP + p++] = base + 0;
            if (m1 && p < PCAP) g_posidx[n * PCAP + p++] = base + 1;
            if (m2 && p < PCAP) g_posidx[n * PCAP + p++] = base + 2;
            if (m3 && p < PCAP) g_posidx[n * PCAP + p++] = base + 3;
        }
    }
    for (int o = 16; o > 0; o >>= 1) {
        contrib += __shfl_down_sync(0xffffffffu, contrib, o);
        pc      += __shfl_down_sync(0xffffffffu, pc, o);
    }
    __shared__ float sw[8];
    __shared__ int   swp[8];
    int wid = threadIdx.x >> 5, lane = threadIdx.x & 31;
    if (lane == 0) { sw[wid] = contrib; swp[wid] = pc; }
    __syncthreads();
    if (threadIdx.x == 0) {
        float t = 0.f; int tp = 0;
#pragma unroll
        for (int j = 0; j < 8; j++) { t += sw[j]; tp += swp[j]; }
        g_partcon[n * 16 + blockIdx.x] = t;
        g_partpos[n * 16 + blockIdx.x] = tp;
    }
}

// ---------------------------------------------------------------------------
// Kernel T: per-row tail. Loc gather over compacted positives (+reset counter)
// then two-level 4096-bin histogram top-k. grid = N_, block = 1024.
// ---------------------------------------------------------------------------
__global__ __launch_bounds__(1024) void kT_tail(const float* __restrict__ ploc,
                                                const float* __restrict__ gloc,
                                                const int*   __restrict__ domain_label,
                                                const float* __restrict__ dboxes,
                                                float* __restrict__ out)
{
    extern __shared__ unsigned dyn[];
    unsigned* s_con  = dyn;              // A4P*4 = 12288 uints (padded with 0u)
    unsigned* s_hist = dyn + A4P * 4;    // 4 * 4096

    __shared__ unsigned s_wc[32];
    __shared__ float    s_redf[32];
    __shared__ int      s_B, s_B2;
    __shared__ unsigned s_kk, s_kk2;
    __shared__ float    s_ps;
    __shared__ int      s_pn;
    __shared__ unsigned s_pcnt;
    __shared__ unsigned s_last;

    const int n   = blockIdx.x;
    const int tid = threadIdx.x;
    const int wid = tid >> 5, lane = tid & 31;
    const int dl  = domain_label[n];
    float rowval = 0.f;

    if (dl == 0) {
        if (tid == 0) {
            float ps = 0.f; int pp = 0;
#pragma unroll
            for (int q = 0; q < 9; q++) { ps += g_partcon[n * 16 + q]; pp += g_partpos[n * 16 + q]; }
            s_ps = ps; s_pn = pp;
            unsigned pcnt = g_poscnt[n];
            s_pcnt = (pcnt > PCAP) ? PCAP : pcnt;
            g_poscnt[n] = 0u;              // reset for next graph replay
        }
#pragma unroll
        for (int q = 0; q < 16; q++) s_hist[q * 1024 + tid] = 0u;
        __syncthreads();
        const int pos = s_pn;

        if (pos > 0) {
            const uint4* gc = (const uint4*)g_con + (size_t)n * A4_;
            unsigned* h1 = s_hist + ((unsigned)wid & 3u) * NB;

            float acc = 0.f;

            // ===== loc gather over compacted positives (~437) =====
            {
                const unsigned pcnt = s_pcnt;
                const float* PLn = ploc + (size_t)n * 4 * A_;
                const float* GLn = gloc + (size_t)n * 4 * A_;
                for (unsigned i = tid; i < pcnt; i += 1024) {
                    int a = g_posidx[n * PCAP + i];
                    float px = PLn[a],            py = PLn[A_ + a];
                    float pw = PLn[2 * A_ + a],   ph = PLn[3 * A_ + a];
                    float gx = GLn[a],            gy = GLn[A_ + a];
                    float gw = GLn[2 * A_ + a],   gh = GLn[3 * A_ + a];
                    float dx = dboxes[a],         dy = dboxes[A_ + a];
                    float dw = dboxes[2 * A_ + a], dh = dboxes[3 * A_ + a];

                    float v0 = 10.f * (gx - dx) / dw;
                    float v1 = 10.f * (gy - dy) / dh;
                    float v2 = 5.f * __logf(gw / dw);
                    float v3 = 5.f * __logf(gh / dh);
                    float d0 = px - v0, d1 = py - v1, d2 = pw - v2, d3 = ph - v3;
                    float ad;
                    ad = fabsf(d0); acc += (ad < 1.f) ? 0.5f * d0 * d0 : ad - 0.5f;
                    ad = fabsf(d1); acc += (ad < 1.f) ? 0.5f * d1 * d1 : ad - 0.5f;
                    ad = fabsf(d2); acc += (ad < 1.f) ? 0.5f * d2 * d2 : ad - 0.5f;
                    ad = fabsf(d3); acc += (ad < 1.f) ? 0.5f * d3 * d3 : ad - 0.5f;
                }
            }

            // ===== phase 1: L2-hot gmem scan -> smem + hist1 =====
#pragma unroll
            for (int chunk = 0; chunk < 3; chunk++) {
                int grp = chunk * 1024 + tid;
                uint4 x = (grp < A4_) ? __ldcg(gc + grp) : make_uint4(0u, 0u, 0u, 0u);
                ((uint4*)s_con)[grp] = x;
                atomicAdd(&h1[x.x >> 20], 1u);
                atomicAdd(&h1[x.y >> 20], 1u);
                atomicAdd(&h1[x.z >> 20], 1u);
                atomicAdd(&h1[x.w >> 20], 1u);
            }
            __syncthreads();

            const unsigned k = (unsigned)((3 * pos > A_) ? A_ : 3 * pos);

            // ===== scan level-1 (4 bins/thread) -> B, kk =====
            {
                unsigned h[4];
#pragma unroll
                for (int q = 0; q < 4; q++)
                    h[q] = s_hist[4 * tid + q] + s_hist[NB + 4 * tid + q]
                         + s_hist[2 * NB + 4 * tid + q] + s_hist[3 * NB + 4 * tid + q];
                unsigned c = h[0] + h[1] + h[2] + h[3];
#pragma unroll
                for (int o = 1; o < 32; o <<= 1) {
                    unsigned uc = __shfl_down_sync(0xffffffffu, c, o);
                    if (lane + o < 32) c += uc;
                }
                if (lane == 0) s_wc[wid] = c;
                __syncthreads();
                if (tid < 32) {
                    unsigned cc = s_wc[tid];
#pragma unroll
                    for (int o = 1; o < 32; o <<= 1) {
                        unsigned uc = __shfl_down_sync(0xffffffffu, cc, o);
                        if (tid + o < 32) cc += uc;
                    }
                    s_wc[tid] = cc;
                }
                __syncthreads();
                unsigned hi = (wid < 31) ? s_wc[wid + 1] : 0u;
                unsigned suf = c + hi;
#pragma unroll
                for (int q = 0; q < 4; q++) {
                    unsigned gtc = suf - h[q];
                    if (k <= suf && k > gtc) { s_B = 4 * tid + q; s_kk = k - gtc; }
                    suf = gtc;
                }
            }
            __syncthreads();
            const unsigned B  = (unsigned)s_B;
            const unsigned kk = s_kk;

#pragma unroll
            for (int q = 0; q < 16; q++) s_hist[q * 1024 + tid] = 0u;
            __syncthreads();

            // ===== phase 2 (smem): above-B sum + hist2 on bucket B =====
#pragma unroll
            for (int chunk = 0; chunk < 3; chunk++) {
                int grp = chunk * 1024 + tid;
                uint4 x = ((const uint4*)s_con)[grp];
#define P2(V)                                                                 \
                {                                                             \
                    unsigned b = (V) >> 20;                                   \
                    if (b > B) acc += __uint_as_float(V);                     \
                    else if (b == B) atomicAdd(&h1[((V) >> 8) & 0xFFFu], 1u); \
                }
                P2(x.x) P2(x.y) P2(x.z) P2(x.w)
#undef P2
            }
            __syncthreads();

            // ===== scan level-2 -> B2, kk2 =====
            {
                unsigned h[4];
#pragma unroll
                for (int q = 0; q < 4; q++)
                    h[q] = s_hist[4 * tid + q] + s_hist[NB + 4 * tid + q]
                         + s_hist[2 * NB + 4 * tid + q] + s_hist[3 * NB + 4 * tid + q];
                unsigned c = h[0] + h[1] + h[2] + h[3];
#pragma unroll
                for (int o = 1; o < 32; o <<= 1) {
                    unsigned uc = __shfl_down_sync(0xffffffffu, c, o);
                    if (lane + o < 32) c += uc;
                }
                if (lane == 0) s_wc[wid] = c;
                __syncthreads();
                if (tid < 32) {
                    unsigned cc = s_wc[tid];
#pragma unroll
                    for (int o = 1; o < 32; o <<= 1) {
                        unsigned uc = __shfl_down_sync(0xffffffffu, cc, o);
                        if (tid + o < 32) cc += uc;
                    }
                    s_wc[tid] = cc;
                }
                __syncthreads();
                unsigned hi = (wid < 31) ? s_wc[wid + 1] : 0u;
                unsigned suf = c + hi;
#pragma unroll
                for (int q = 0; q < 4; q++) {
                    unsigned gtc = suf - h[q];
                    if (kk <= suf && kk > gtc) { s_B2 = 4 * tid + q; s_kk2 = kk - gtc; }
                    suf = gtc;
                }
            }
            __syncthreads();
            const unsigned B2  = (unsigned)s_B2;
            const unsigned kk2 = s_kk2;

            // ===== phase 3 (smem): bucket-B above-B2 sum =====
#pragma unroll
            for (int chunk = 0; chunk < 3; chunk++) {
                int grp = chunk * 1024 + tid;
                uint4 x = ((const uint4*)s_con)[grp];
#define P3(V)                                                                 \
                if (((V) >> 20) == B && (((V) >> 8) & 0xFFFu) > B2)           \
                    acc += __uint_as_float(V);
                P3(x.x) P3(x.y) P3(x.z) P3(x.w)
#undef P3
            }

            // ===== single block reduce =====
            for (int o = 16; o > 0; o >>= 1) acc += __shfl_down_sync(0xffffffffu, acc, o);
            if (lane == 0) s_redf[wid] = acc;
            __syncthreads();
            if (tid == 0) {
                float t = 0.f;
#pragma unroll
                for (int q = 0; q < 32; q++) t += s_redf[q];
                float lb = __uint_as_float((B << 20) | (B2 << 8));
                rowval = (s_ps + t + (float)kk2 * lb) / (float)pos;
            }
        }
    }

    if (tid == 0) {
        g_row[n] = rowval;
        __threadfence();
        unsigned old = atomicAdd(&g_count, 1u);
        s_last = (old == N_ - 1u) ? 1u : 0u;
    }
    __syncthreads();

    if (s_last) {
        __threadfence();
        float v = (tid < N_) ? g_row[tid] : 0.f;
        for (int o = 16; o > 0; o >>= 1) v += __shfl_down_sync(0xffffffffu, v, o);
        if (lane == 0) s_redf[wid] = v;
        __syncthreads();
        if (tid == 0) {
            float t = s_redf[0] + s_redf[1] + s_redf[2] + s_redf[3];
            out[0] = t / (float)N_;
            g_count = 0u;   // reset for next graph replay
        }
    }
}

extern "C" void kernel_launch(void* const* d_in, const int* in_sizes, int n_in,
                              void* d_out, int out_size)
{
    const float* ploc         = (const float*)d_in[0];
    const float* plabel       = (const float*)d_in[1];
    const float* gloc         = (const float*)d_in[2];
    const int*   glabel       = (const int*)  d_in[3];
    const int*   domain_label = (const int*)  d_in[4];
    const float* dboxes       = (const float*)d_in[5];
    float* out = (float*)d_out;

    cudaFuncSetAttribute(kT_tail, cudaFuncAttributeMaxDynamicSharedMemorySize, DYN_BYTES);

    dim3 g1(9, N_);
    kA_focal<<<g1, 256>>>(plabel, glabel, domain_label);
    kT_tail<<<N_, 1024, DYN_BYTES>>>(ploc, gloc, domain_label, dboxes, out);
}

// round 14
// speedup vs baseline: 1.0741x; 1.0741x over previous
#include <cuda_runtime.h>
#include <cuda_bf16.h>
#include <cstdint>

#define N_ 128
#define C_ 81
#define A_ 8732
#define A4_ 2183          // A_/4 exactly
#define A4P 3072          // padded uint4 groups (3 * 1024)
#define NB 4096
#define DYN_BYTES ((A4P * 4 + 4 * NB) * 4)   // s_con + 4 hist replicas = 114688 B

// Scratch (device globals — no allocations allowed)
__device__ unsigned g_con[N_ * A_];
__device__ float    g_partcon[N_ * 16];
__device__ int      g_partpos[N_ * 16];
__device__ float    g_partsl1[N_ * 16];
__device__ float    g_row[N_];
__device__ unsigned g_count;               // self-resetting

// ---------------------------------------------------------------------------
// Kernel B: masked smooth-L1 partial sums — UNCONDITIONAL streaming loads
// (only ~20 MB for dl==0 rows; straight-line float4 loads give full MLP,
// the positive mask gates only the accumulate). Two phases (xy then wh)
// keep the live register set small. grid = (9, N), block = 256.
// ---------------------------------------------------------------------------
__global__ __launch_bounds__(256) void kB_loc(const float* __restrict__ ploc,
                                              const float* __restrict__ gloc,
                                              const int*   __restrict__ glabel,
                                              const int*   __restrict__ domain_label,
                                              const float* __restrict__ dboxes)
{
    const int n = blockIdx.y;
    if (domain_label[n] != 0) return;

    int idx = blockIdx.x * 256 + threadIdx.x;
    bool valid = (idx < A4_);
    int ii = valid ? idx : (A4_ - 1);

    int4 g = ((const int4*)(glabel + (size_t)n * A_))[ii];
    float k0 = (valid && g.x > 0) ? 1.f : 0.f;
    float k1 = (valid && g.y > 0) ? 1.f : 0.f;
    float k2 = (valid && g.z > 0) ? 1.f : 0.f;
    float k3 = (valid && g.w > 0) ? 1.f : 0.f;

    const float4* PL = (const float4*)(ploc + (size_t)n * 4 * A_);
    const float4* GL = (const float4*)(gloc + (size_t)n * 4 * A_);
    const float4* DB = (const float4*)dboxes;

    float contrib = 0.f;

#define SL1_TERM(D) { float ad = fabsf(D); lsum += (ad < 1.f) ? 0.5f*(D)*(D) : ad - 0.5f; }

    // widths/heights needed by both phases
    float4 dbw = DB[2 * A4_ + ii], dbh = DB[3 * A4_ + ii];

    // ---- phase 1: xy terms ----
    {
        float4 plx = PL[0 * A4_ + ii], ply = PL[1 * A4_ + ii];
        float4 glx = GL[0 * A4_ + ii], gly = GL[1 * A4_ + ii];
        float4 dbx = DB[0 * A4_ + ii], dby = DB[1 * A4_ + ii];
#define XY_LANE(K, PX, PY, GX, GY, DX, DY, DW, DH)                        \
        {                                                                 \
            float lsum = 0.f;                                             \
            float d0 = PX - 10.f * (GX - DX) / DW;                        \
            float d1 = PY - 10.f * (GY - DY) / DH;                        \
            SL1_TERM(d0) SL1_TERM(d1)                                     \
            contrib += K * lsum;                                          \
        }
        XY_LANE(k0, plx.x, ply.x, glx.x, gly.x, dbx.x, dby.x, dbw.x, dbh.x)
        XY_LANE(k1, plx.y, ply.y, glx.y, gly.y, dbx.y, dby.y, dbw.y, dbh.y)
        XY_LANE(k2, plx.z, ply.z, glx.z, gly.z, dbx.z, dby.z, dbw.z, dbh.z)
        XY_LANE(k3, plx.w, ply.w, glx.w, gly.w, dbx.w, dby.w, dbw.w, dbh.w)
#undef XY_LANE
    }

    // ---- phase 2: wh terms ----
    {
        float4 plw = PL[2 * A4_ + ii], plh = PL[3 * A4_ + ii];
        float4 glw = GL[2 * A4_ + ii], glh = GL[3 * A4_ + ii];
#define WH_LANE(K, PW, PH, GW, GH, DW, DH)                                \
        {                                                                 \
            float lsum = 0.f;                                             \
            float d2 = PW - 5.f * __logf(GW / DW);                        \
            float d3 = PH - 5.f * __logf(GH / DH);                        \
            SL1_TERM(d2) SL1_TERM(d3)                                     \
            contrib += K * lsum;                                          \
        }
        WH_LANE(k0, plw.x, plh.x, glw.x, glh.x, dbw.x, dbh.x)
        WH_LANE(k1, plw.y, plh.y, glw.y, glh.y, dbw.y, dbh.y)
        WH_LANE(k2, plw.z, plh.z, glw.z, glh.z, dbw.z, dbh.z)
        WH_LANE(k3, plw.w, plh.w, glw.w, glh.w, dbw.w, dbh.w)
#undef WH_LANE
    }
#undef SL1_TERM

    for (int o = 16; o > 0; o >>= 1)
        contrib += __shfl_down_sync(0xffffffffu, contrib, o);
    __shared__ float sw[8];
    int wid = threadIdx.x >> 5, lane = threadIdx.x & 31;
    if (lane == 0) sw[wid] = contrib;
    __syncthreads();
    if (threadIdx.x == 0) {
        float t = 0.f;
#pragma unroll
        for (int j = 0; j < 8; j++) t += sw[j];
        g_partsl1[n * 16 + blockIdx.x] = t;
    }
}

// ---------------------------------------------------------------------------
// Kernel A: focal loss per anchor (clean — at its traffic floor, untouched).
// grid = (9, N), block = 256. Whole block exits when domain_label != 0.
// ---------------------------------------------------------------------------
__global__ __launch_bounds__(256, 8) void kA_focal(const float* __restrict__ plabel,
                                                   const int*   __restrict__ glabel,
                                                   const int*   __restrict__ domain_label)
{
    const int n = blockIdx.y;
    if (domain_label[n] != 0) return;

    int idx = blockIdx.x * 256 + threadIdx.x;
    bool valid = (idx < A4_);
    int ii = valid ? idx : (A4_ - 1);

    const float4* P = (const float4*)(plabel + (size_t)n * C_ * A_) + ii;
    int4 g = ((const int4*)(glabel + (size_t)n * A_))[ii];

    float4 s  = make_float4(0.f, 0.f, 0.f, 0.f);
    float4 xg = make_float4(0.f, 0.f, 0.f, 0.f);
#pragma unroll 3
    for (int c = 0; c < C_; c++) {
        float4 x = __ldcs(P);
        P += A4_;
        if (c == g.x) xg.x = x.x;
        if (c == g.y) xg.y = x.y;
        if (c == g.z) xg.z = x.z;
        if (c == g.w) xg.w = x.w;
        s.x += __expf(x.x); s.y += __expf(x.y);
        s.z += __expf(x.z); s.w += __expf(x.w);
    }

    float lp0 = xg.x - __logf(s.x), lp1 = xg.y - __logf(s.y);
    float lp2 = xg.z - __logf(s.z), lp3 = xg.w - __logf(s.w);
    float o0 = 1.f - __expf(lp0), o1 = 1.f - __expf(lp1);
    float o2 = 1.f - __expf(lp2), o3 = 1.f - __expf(lp3);
    float c0 = -0.25f * o0 * o0 * lp0;
    float c1 = -0.25f * o1 * o1 * lp1;
    float c2 = -0.25f * o2 * o2 * lp2;
    float c3 = -0.25f * o3 * o3 * lp3;

    bool m0 = g.x > 0, m1 = g.y > 0, m2 = g.z > 0, m3 = g.w > 0;

    uint4 cw;
    cw.x = m0 ? 0u : __float_as_uint(c0);
    cw.y = m1 ? 0u : __float_as_uint(c1);
    cw.z = m2 ? 0u : __float_as_uint(c2);
    cw.w = m3 ? 0u : __float_as_uint(c3);
    ((uint4*)g_con)[(size_t)n * A4_ + ii] = cw;

    float contrib = 0.f;
    int pc = 0;
    if (valid) {
        if (m0) { contrib += c0; pc++; }
        if (m1) { contrib += c1; pc++; }
        if (m2) { contrib += c2; pc++; }
        if (m3) { contrib += c3; pc++; }
    }
    for (int o = 16; o > 0; o >>= 1) {
        contrib += __shfl_down_sync(0xffffffffu, contrib, o);
        pc      += __shfl_down_sync(0xffffffffu, pc, o);
    }
    __shared__ float sw[8];
    __shared__ int   swp[8];
    int wid = threadIdx.x >> 5, lane = threadIdx.x & 31;
    if (lane == 0) { sw[wid] = contrib; swp[wid] = pc; }
    __syncthreads();
    if (threadIdx.x == 0) {
        float t = 0.f; int tp = 0;
#pragma unroll
        for (int j = 0; j < 8; j++) { t += sw[j]; tp += swp[j]; }
        g_partcon[n * 16 + blockIdx.x] = t;
        g_partpos[n * 16 + blockIdx.x] = tp;
    }
}

// ---------------------------------------------------------------------------
// Kernel T: select-only per-row tail (two-level 4096-bin histogram top-k).
// grid = N_, block = 1024. Last-arriving CTA computes the mean.
// ---------------------------------------------------------------------------
__global__ __launch_bounds__(1024) void kT_tail(const int* __restrict__ domain_label,
                                                float* __restrict__ out)
{
    extern __shared__ unsigned dyn[];
    unsigned* s_con  = dyn;              // A4P*4 = 12288 uints (padded with 0u)
    unsigned* s_hist = dyn + A4P * 4;    // 4 * 4096

    __shared__ unsigned s_wc[32];
    __shared__ float    s_redf[32];
    __shared__ int      s_B, s_B2;
    __shared__ unsigned s_kk, s_kk2;
    __shared__ float    s_ps;
    __shared__ int      s_pn;
    __shared__ unsigned s_last;

    const int n   = blockIdx.x;
    const int tid = threadIdx.x;
    const int wid = tid >> 5, lane = tid & 31;
    const int dl  = domain_label[n];
    float rowval = 0.f;

    if (dl == 0) {
        if (tid == 0) {
            float ps = 0.f; int pp = 0;
#pragma unroll
            for (int q = 0; q < 9; q++) {
                ps += g_partcon[n * 16 + q] + g_partsl1[n * 16 + q];
                pp += g_partpos[n * 16 + q];
            }
            s_ps = ps; s_pn = pp;
        }
#pragma unroll
        for (int q = 0; q < 16; q++) s_hist[q * 1024 + tid] = 0u;
        __syncthreads();
        const int pos = s_pn;

        if (pos > 0) {
            const uint4* gc = (const uint4*)g_con + (size_t)n * A4_;
            unsigned* h1 = s_hist + ((unsigned)wid & 3u) * NB;

            float acc = 0.f;

            // ===== phase 1: L2-hot gmem scan -> smem + hist1 =====
#pragma unroll
            for (int chunk = 0; chunk < 3; chunk++) {
                int grp = chunk * 1024 + tid;
                uint4 x = (grp < A4_) ? __ldcg(gc + grp) : make_uint4(0u, 0u, 0u, 0u);
                ((uint4*)s_con)[grp] = x;
                atomicAdd(&h1[x.x >> 20], 1u);
                atomicAdd(&h1[x.y >> 20], 1u);
                atomicAdd(&h1[x.z >> 20], 1u);
                atomicAdd(&h1[x.w >> 20], 1u);
            }
            __syncthreads();

            const unsigned k = (unsigned)((3 * pos > A_) ? A_ : 3 * pos);

            // ===== scan level-1 (4 bins/thread) -> B, kk =====
            {
                unsigned h[4];
#pragma unroll
                for (int q = 0; q < 4; q++)
                    h[q] = s_hist[4 * tid + q] + s_hist[NB + 4 * tid + q]
                         + s_hist[2 * NB + 4 * tid + q] + s_hist[3 * NB + 4 * tid + q];
                unsigned c = h[0] + h[1] + h[2] + h[3];
#pragma unroll
                for (int o = 1; o < 32; o <<= 1) {
                    unsigned uc = __shfl_down_sync(0xffffffffu, c, o);
                    if (lane + o < 32) c += uc;
                }
                if (lane == 0) s_wc[wid] = c;
                __syncthreads();
                if (tid < 32) {
                    unsigned cc = s_wc[tid];
#pragma unroll
                    for (int o = 1; o < 32; o <<= 1) {
                        unsigned uc = __shfl_down_sync(0xffffffffu, cc, o);
                        if (tid + o < 32) cc += uc;
                    }
                    s_wc[tid] = cc;
                }
                __syncthreads();
                unsigned hi = (wid < 31) ? s_wc[wid + 1] : 0u;
                unsigned suf = c + hi;
#pragma unroll
                for (int q = 0; q < 4; q++) {
                    unsigned gtc = suf - h[q];
                    if (k <= suf && k > gtc) { s_B = 4 * tid + q; s_kk = k - gtc; }
                    suf = gtc;
                }
            }
            __syncthreads();
            const unsigned B  = (unsigned)s_B;
            const unsigned kk = s_kk;

#pragma unroll
            for (int q = 0; q < 16; q++) s_hist[q * 1024 + tid] = 0u;
            __syncthreads();

            // ===== phase 2 (smem): above-B sum + hist2 on bucket B =====
#pragma unroll
            for (int chunk = 0; chunk < 3; chunk++) {
                int grp = chunk * 1024 + tid;
                uint4 x = ((const uint4*)s_con)[grp];
#define P2(V)                                                                 \
                {                                                             \
                    unsigned b = (V) >> 20;                                   \
                    if (b > B) acc += __uint_as_float(V);                     \
                    else if (b == B) atomicAdd(&h1[((V) >> 8) & 0xFFFu], 1u); \
                }
                P2(x.x) P2(x.y) P2(x.z) P2(x.w)
#undef P2
            }
            __syncthreads();

            // ===== scan level-2 -> B2, kk2 =====
            {
                unsigned h[4];
#pragma unroll
                for (int q = 0; q < 4; q++)
                    h[q] = s_hist[4 * tid + q] + s_hist[NB + 4 * tid + q]
                         + s_hist[2 * NB + 4 * tid + q] + s_hist[3 * NB + 4 * tid + q];
                unsigned c = h[0] + h[1] + h[2] + h[3];
#pragma unroll
                for (int o = 1; o < 32; o <<= 1) {
                    unsigned uc = __shfl_down_sync(0xffffffffu, c, o);
                    if (lane + o < 32) c += uc;
                }
                if (lane == 0) s_wc[wid] = c;
                __syncthreads();
                if (tid < 32) {
                    unsigned cc = s_wc[tid];
#pragma unroll
                    for (int o = 1; o < 32; o <<= 1) {
                        unsigned uc = __shfl_down_sync(0xffffffffu, cc, o);
                        if (tid + o < 32) cc += uc;
                    }
                    s_wc[tid] = cc;
                }
                __syncthreads();
                unsigned hi = (wid < 31) ? s_wc[wid + 1] : 0u;
                unsigned suf = c + hi;
#pragma unroll
                for (int q = 0; q < 4; q++) {
                    unsigned gtc = suf - h[q];
                    if (kk <= suf && kk > gtc) { s_B2 = 4 * tid + q; s_kk2 = kk - gtc; }
                    suf = gtc;
                }
            }
            __syncthreads();
            const unsigned B2  = (unsigned)s_B2;
            const unsigned kk2 = s_kk2;

            // ===== phase 3 (smem): bucket-B above-B2 sum =====
#pragma unroll
            for (int chunk = 0; chunk < 3; chunk++) {
                int grp = chunk * 1024 + tid;
                uint4 x = ((const uint4*)s_con)[grp];
#define P3(V)                                                                 \
                if (((V) >> 20) == B && (((V) >> 8) & 0xFFFu) > B2)           \
                    acc += __uint_as_float(V);
                P3(x.x) P3(x.y) P3(x.z) P3(x.w)
#undef P3
            }

            // ===== single block reduce =====
            for (int o = 16; o > 0; o >>= 1) acc += __shfl_down_sync(0xffffffffu, acc, o);
            if (lane == 0) s_redf[wid] = acc;
            __syncthreads();
            if (tid == 0) {
                float t = 0.f;
#pragma unroll
                for (int q = 0; q < 32; q++) t += s_redf[q];
                float lb = __uint_as_float((B << 20) | (B2 << 8));
                rowval = (s_ps + t + (float)kk2 * lb) / (float)pos;
            }
        }
    }

    if (tid == 0) {
        g_row[n] = rowval;
        __threadfence();
        unsigned old = atomicAdd(&g_count, 1u);
        s_last = (old == N_ - 1u) ? 1u : 0u;
    }
    __syncthreads();

    if (s_last) {
        __threadfence();
        float v = (tid < N_) ? g_row[tid] : 0.f;
        for (int o = 16; o > 0; o >>= 1) v += __shfl_down_sync(0xffffffffu, v, o);
        if (lane == 0) s_redf[wid] = v;
        __syncthreads();
        if (tid == 0) {
            float t = s_redf[0] + s_redf[1] + s_redf[2] + s_redf[3];
            out[0] = t / (float)N_;
            g_count = 0u;   // reset for next graph replay
        }
    }
}

extern "C" void kernel_launch(void* const* d_in, const int* in_sizes, int n_in,
                              void* d_out, int out_size)
{
    const float* ploc         = (const float*)d_in[0];
    const float* plabel       = (const float*)d_in[1];
    const float* gloc         = (const float*)d_in[2];
    const int*   glabel       = (const int*)  d_in[3];
    const int*   domain_label = (const int*)  d_in[4];
    const float* dboxes       = (const float*)d_in[5];
    float* out = (float*)d_out;

    cudaFuncSetAttribute(kT_tail, cudaFuncAttributeMaxDynamicSharedMemorySize, DYN_BYTES);

    dim3 g1(9, N_);
    kB_loc<<<g1, 256>>>(ploc, gloc, glabel, domain_label, dboxes);
    kA_focal<<<g1, 256>>>(plabel, glabel, domain_label);
    kT_tail<<<N_, 1024, DYN_BYTES>>>(domain_label, out);
}

// round 15
// speedup vs baseline: 1.0784x; 1.0040x over previous
#include <cuda_runtime.h>
#include <cuda_bf16.h>
#include <cstdint>

#define N_ 128
#define C_ 81
#define A_ 8732
#define A4_ 2183          // A_/4 exactly
#define A4P 3072          // padded uint4 groups (3 * 1024)
#define NB 4096
#define DYN_BYTES ((A4P * 4 + 4 * NB) * 4)   // s_con + 4 hist replicas = 114688 B

// Scratch (device globals — no allocations allowed)
__device__ unsigned g_con[N_ * A_];
__device__ float    g_partcon[N_ * 16];
__device__ int      g_partpos[N_ * 16];
__device__ float    g_partsl1[N_ * 16];
__device__ float    g_row[N_];
__device__ unsigned g_count;               // self-resetting

// ---------------------------------------------------------------------------
// Kernel B: masked smooth-L1 partial sums (R12 group-skip variant — lowest
// traffic; runs CONCURRENTLY with kA via graph fork). grid = (9, N), 256 thr.
// ---------------------------------------------------------------------------
__global__ __launch_bounds__(256) void kB_loc(const float* __restrict__ ploc,
                                              const float* __restrict__ gloc,
                                              const int*   __restrict__ glabel,
                                              const int*   __restrict__ domain_label,
                                              const float* __restrict__ dboxes)
{
    const int n = blockIdx.y;
    if (domain_label[n] != 0) return;

    int idx = blockIdx.x * 256 + threadIdx.x;
    bool valid = (idx < A4_);
    int ii = valid ? idx : (A4_ - 1);

    int4 g = ((const int4*)(glabel + (size_t)n * A_))[ii];
    bool m0 = g.x > 0, m1 = g.y > 0, m2 = g.z > 0, m3 = g.w > 0;

    float contrib = 0.f;
    if (valid && (m0 | m1 | m2 | m3)) {
        const float4* PL = (const float4*)(ploc + (size_t)n * 4 * A_);
        const float4* GL = (const float4*)(gloc + (size_t)n * 4 * A_);
        const float4* DB = (const float4*)dboxes;

        float4 plx = PL[0 * A4_ + ii], ply = PL[1 * A4_ + ii];
        float4 plw = PL[2 * A4_ + ii], plh = PL[3 * A4_ + ii];
        float4 glx = GL[0 * A4_ + ii], gly = GL[1 * A4_ + ii];
        float4 glw = GL[2 * A4_ + ii], glh = GL[3 * A4_ + ii];
        float4 dbx = DB[0 * A4_ + ii], dby = DB[1 * A4_ + ii];
        float4 dbw = DB[2 * A4_ + ii], dbh = DB[3 * A4_ + ii];

#define SL1_LANE(M, PX, PY, PW, PH, GX, GY, GW, GH, DX, DY, DW, DH)       \
        if (M) {                                                          \
            float v0 = 10.f * (GX - DX) / DW;                             \
            float v1 = 10.f * (GY - DY) / DH;                             \
            float v2 = 5.f * __logf(GW / DW);                             \
            float v3 = 5.f * __logf(GH / DH);                             \
            float d0 = PX - v0, d1 = PY - v1, d2 = PW - v2, d3 = PH - v3; \
            float ad;                                                     \
            ad = fabsf(d0); contrib += (ad < 1.f) ? 0.5f*d0*d0 : ad-0.5f; \
            ad = fabsf(d1); contrib += (ad < 1.f) ? 0.5f*d1*d1 : ad-0.5f; \
            ad = fabsf(d2); contrib += (ad < 1.f) ? 0.5f*d2*d2 : ad-0.5f; \
            ad = fabsf(d3); contrib += (ad < 1.f) ? 0.5f*d3*d3 : ad-0.5f; \
        }
        SL1_LANE(m0, plx.x, ply.x, plw.x, plh.x, glx.x, gly.x, glw.x, glh.x, dbx.x, dby.x, dbw.x, dbh.x)
        SL1_LANE(m1, plx.y, ply.y, plw.y, plh.y, glx.y, gly.y, glw.y, glh.y, dbx.y, dby.y, dbw.y, dbh.y)
        SL1_LANE(m2, plx.z, ply.z, plw.z, plh.z, glx.z, gly.z, glw.z, glh.z, dbx.z, dby.z, dbw.z, dbh.z)
        SL1_LANE(m3, plx.w, ply.w, plw.w, plh.w, glx.w, gly.w, glw.w, glh.w, dbx.w, dby.w, dbw.w, dbh.w)
#undef SL1_LANE
    }

    for (int o = 16; o > 0; o >>= 1)
        contrib += __shfl_down_sync(0xffffffffu, contrib, o);
    __shared__ float sw[8];
    int wid = threadIdx.x >> 5, lane = threadIdx.x & 31;
    if (lane == 0) sw[wid] = contrib;
    __syncthreads();
    if (threadIdx.x == 0) {
        float t = 0.f;
#pragma unroll
        for (int j = 0; j < 8; j++) t += sw[j];
        g_partsl1[n * 16 + blockIdx.x] = t;
    }
}

// ---------------------------------------------------------------------------
// Kernel A: focal loss per anchor (clean — at its traffic floor, untouched).
// ---------------------------------------------------------------------------
__global__ __launch_bounds__(256, 8) void kA_focal(const float* __restrict__ plabel,
                                                   const int*   __restrict__ glabel,
                                                   const int*   __restrict__ domain_label)
{
    const int n = blockIdx.y;
    if (domain_label[n] != 0) return;

    int idx = blockIdx.x * 256 + threadIdx.x;
    bool valid = (idx < A4_);
    int ii = valid ? idx : (A4_ - 1);

    const float4* P = (const float4*)(plabel + (size_t)n * C_ * A_) + ii;
    int4 g = ((const int4*)(glabel + (size_t)n * A_))[ii];

    float4 s  = make_float4(0.f, 0.f, 0.f, 0.f);
    float4 xg = make_float4(0.f, 0.f, 0.f, 0.f);
#pragma unroll 3
    for (int c = 0; c < C_; c++) {
        float4 x = __ldcs(P);
        P += A4_;
        if (c == g.x) xg.x = x.x;
        if (c == g.y) xg.y = x.y;
        if (c == g.z) xg.z = x.z;
        if (c == g.w) xg.w = x.w;
        s.x += __expf(x.x); s.y += __expf(x.y);
        s.z += __expf(x.z); s.w += __expf(x.w);
    }

    float lp0 = xg.x - __logf(s.x), lp1 = xg.y - __logf(s.y);
    float lp2 = xg.z - __logf(s.z), lp3 = xg.w - __logf(s.w);
    float o0 = 1.f - __expf(lp0), o1 = 1.f - __expf(lp1);
    float o2 = 1.f - __expf(lp2), o3 = 1.f - __expf(lp3);
    float c0 = -0.25f * o0 * o0 * lp0;
    float c1 = -0.25f * o1 * o1 * lp1;
    float c2 = -0.25f * o2 * o2 * lp2;
    float c3 = -0.25f * o3 * o3 * lp3;

    bool m0 = g.x > 0, m1 = g.y > 0, m2 = g.z > 0, m3 = g.w > 0;

    uint4 cw;
    cw.x = m0 ? 0u : __float_as_uint(c0);
    cw.y = m1 ? 0u : __float_as_uint(c1);
    cw.z = m2 ? 0u : __float_as_uint(c2);
    cw.w = m3 ? 0u : __float_as_uint(c3);
    ((uint4*)g_con)[(size_t)n * A4_ + ii] = cw;

    float contrib = 0.f;
    int pc = 0;
    if (valid) {
        if (m0) { contrib += c0; pc++; }
        if (m1) { contrib += c1; pc++; }
        if (m2) { contrib += c2; pc++; }
        if (m3) { contrib += c3; pc++; }
    }
    for (int o = 16; o > 0; o >>= 1) {
        contrib += __shfl_down_sync(0xffffffffu, contrib, o);
        pc      += __shfl_down_sync(0xffffffffu, pc, o);
    }
    __shared__ float sw[8];
    __shared__ int   swp[8];
    int wid = threadIdx.x >> 5, lane = threadIdx.x & 31;
    if (lane == 0) { sw[wid] = contrib; swp[wid] = pc; }
    __syncthreads();
    if (threadIdx.x == 0) {
        float t = 0.f; int tp = 0;
#pragma unroll
        for (int j = 0; j < 8; j++) { t += sw[j]; tp += swp[j]; }
        g_partcon[n * 16 + blockIdx.x] = t;
        g_partpos[n * 16 + blockIdx.x] = tp;
    }
}

// ---------------------------------------------------------------------------
// Kernel T: select-only per-row tail (two-level 4096-bin histogram top-k).
// grid = N_, block = 1024. Last-arriving CTA computes the mean.
// ---------------------------------------------------------------------------
__global__ __launch_bounds__(1024) void kT_tail(const int* __restrict__ domain_label,
                                                float* __restrict__ out)
{
    extern __shared__ unsigned dyn[];
    unsigned* s_con  = dyn;              // A4P*4 = 12288 uints (padded with 0u)
    unsigned* s_hist = dyn + A4P * 4;    // 4 * 4096

    __shared__ unsigned s_wc[32];
    __shared__ float    s_redf[32];
    __shared__ int      s_B, s_B2;
    __shared__ unsigned s_kk, s_kk2;
    __shared__ float    s_ps;
    __shared__ int      s_pn;
    __shared__ unsigned s_last;

    const int n   = blockIdx.x;
    const int tid = threadIdx.x;
    const int wid = tid >> 5, lane = tid & 31;
    const int dl  = domain_label[n];
    float rowval = 0.f;

    if (dl == 0) {
        if (tid == 0) {
            float ps = 0.f; int pp = 0;
#pragma unroll
            for (int q = 0; q < 9; q++) {
                ps += g_partcon[n * 16 + q] + g_partsl1[n * 16 + q];
                pp += g_partpos[n * 16 + q];
            }
            s_ps = ps; s_pn = pp;
        }
#pragma unroll
        for (int q = 0; q < 16; q++) s_hist[q * 1024 + tid] = 0u;
        __syncthreads();
        const int pos = s_pn;

        if (pos > 0) {
            const uint4* gc = (const uint4*)g_con + (size_t)n * A4_;
            unsigned* h1 = s_hist + ((unsigned)wid & 3u) * NB;

            float acc = 0.f;

            // ===== phase 1: L2-hot gmem scan -> smem + hist1 =====
#pragma unroll
            for (int chunk = 0; chunk < 3; chunk++) {
                int grp = chunk * 1024 + tid;
                uint4 x = (grp < A4_) ? __ldcg(gc + grp) : make_uint4(0u, 0u, 0u, 0u);
                ((uint4*)s_con)[grp] = x;
                atomicAdd(&h1[x.x >> 20], 1u);
                atomicAdd(&h1[x.y >> 20], 1u);
                atomicAdd(&h1[x.z >> 20], 1u);
                atomicAdd(&h1[x.w >> 20], 1u);
            }
            __syncthreads();

            const unsigned k = (unsigned)((3 * pos > A_) ? A_ : 3 * pos);

            // ===== scan level-1 (4 bins/thread) -> B, kk =====
            {
                unsigned h[4];
#pragma unroll
                for (int q = 0; q < 4; q++)
                    h[q] = s_hist[4 * tid + q] + s_hist[NB + 4 * tid + q]
                         + s_hist[2 * NB + 4 * tid + q] + s_hist[3 * NB + 4 * tid + q];
                unsigned c = h[0] + h[1] + h[2] + h[3];
#pragma unroll
                for (int o = 1; o < 32; o <<= 1) {
                    unsigned uc = __shfl_down_sync(0xffffffffu, c, o);
                    if (lane + o < 32) c += uc;
                }
                if (lane == 0) s_wc[wid] = c;
                __syncthreads();
                if (tid < 32) {
                    unsigned cc = s_wc[tid];
#pragma unroll
                    for (int o = 1; o < 32; o <<= 1) {
                        unsigned uc = __shfl_down_sync(0xffffffffu, cc, o);
                        if (tid + o < 32) cc += uc;
                    }
                    s_wc[tid] = cc;
                }
                __syncthreads();
                unsigned hi = (wid < 31) ? s_wc[wid + 1] : 0u;
                unsigned suf = c + hi;
#pragma unroll
                for (int q = 0; q < 4; q++) {
                    unsigned gtc = suf - h[q];
                    if (k <= suf && k > gtc) { s_B = 4 * tid + q; s_kk = k - gtc; }
                    suf = gtc;
                }
            }
            __syncthreads();
            const unsigned B  = (unsigned)s_B;
            const unsigned kk = s_kk;

#pragma unroll
            for (int q = 0; q < 16; q++) s_hist[q * 1024 + tid] = 0u;
            __syncthreads();

            // ===== phase 2 (smem): above-B sum + hist2 on bucket B =====
#pragma unroll
            for (int chunk = 0; chunk < 3; chunk++) {
                int grp = chunk * 1024 + tid;
                uint4 x = ((const uint4*)s_con)[grp];
#define P2(V)                                                                 \
                {                                                             \
                    unsigned b = (V) >> 20;                                   \
                    if (b > B) acc += __uint_as_float(V);                     \
                    else if (b == B) atomicAdd(&h1[((V) >> 8) & 0xFFFu], 1u); \
                }
                P2(x.x) P2(x.y) P2(x.z) P2(x.w)
#undef P2
            }
            __syncthreads();

            // ===== scan level-2 -> B2, kk2 =====
            {
                unsigned h[4];
#pragma unroll
                for (int q = 0; q < 4; q++)
                    h[q] = s_hist[4 * tid + q] + s_hist[NB + 4 * tid + q]
                         + s_hist[2 * NB + 4 * tid + q] + s_hist[3 * NB + 4 * tid + q];
                unsigned c = h[0] + h[1] + h[2] + h[3];
#pragma unroll
                for (int o = 1; o < 32; o <<= 1) {
                    unsigned uc = __shfl_down_sync(0xffffffffu, c, o);
                    if (lane + o < 32) c += uc;
                }
                if (lane == 0) s_wc[wid] = c;
                __syncthreads();
                if (tid < 32) {
                    unsigned cc = s_wc[tid];
#pragma unroll
                    for (int o = 1; o < 32; o <<= 1) {
                        unsigned uc = __shfl_down_sync(0xffffffffu, cc, o);
                        if (tid + o < 32) cc += uc;
                    }
                    s_wc[tid] = cc;
                }
                __syncthreads();
                unsigned hi = (wid < 31) ? s_wc[wid + 1] : 0u;
                unsigned suf = c + hi;
#pragma unroll
                for (int q = 0; q < 4; q++) {
                    unsigned gtc = suf - h[q];
                    if (kk <= suf && kk > gtc) { s_B2 = 4 * tid + q; s_kk2 = kk - gtc; }
                    suf = gtc;
                }
            }
            __syncthreads();
            const unsigned B2  = (unsigned)s_B2;
            const unsigned kk2 = s_kk2;

            // ===== phase 3 (smem): bucket-B above-B2 sum =====
#pragma unroll
            for (int chunk = 0; chunk < 3; chunk++) {
                int grp = chunk * 1024 + tid;
                uint4 x = ((const uint4*)s_con)[grp];
#define P3(V)                                                                 \
                if (((V) >> 20) == B && (((V) >> 8) & 0xFFFu) > B2)           \
                    acc += __uint_as_float(V);
                P3(x.x) P3(x.y) P3(x.z) P3(x.w)
#undef P3
            }

            // ===== single block reduce =====
            for (int o = 16; o > 0; o >>= 1) acc += __shfl_down_sync(0xffffffffu, acc, o);
            if (lane == 0) s_redf[wid] = acc;
            __syncthreads();
            if (tid == 0) {
                float t = 0.f;
#pragma unroll
                for (int q = 0; q < 32; q++) t += s_redf[q];
                float lb = __uint_as_float((B << 20) | (B2 << 8));
                rowval = (s_ps + t + (float)kk2 * lb) / (float)pos;
            }
        }
    }

    if (tid == 0) {
        g_row[n] = rowval;
        __threadfence();
        unsigned old = atomicAdd(&g_count, 1u);
        s_last = (old == N_ - 1u) ? 1u : 0u;
    }
    __syncthreads();

    if (s_last) {
        __threadfence();
        float v = (tid < N_) ? g_row[tid] : 0.f;
        for (int o = 16; o > 0; o >>= 1) v += __shfl_down_sync(0xffffffffu, v, o);
        if (lane == 0) s_redf[wid] = v;
        __syncthreads();
        if (tid == 0) {
            float t = s_redf[0] + s_redf[1] + s_redf[2] + s_redf[3];
            out[0] = t / (float)N_;
            g_count = 0u;   // reset for next graph replay
        }
    }
}

extern "C" void kernel_launch(void* const* d_in, const int* in_sizes, int n_in,
                              void* d_out, int out_size)
{
    const float* ploc         = (const float*)d_in[0];
    const float* plabel       = (const float*)d_in[1];
    const float* gloc         = (const float*)d_in[2];
    const int*   glabel       = (const int*)  d_in[3];
    const int*   domain_label = (const int*)  d_in[4];
    const float* dboxes       = (const float*)d_in[5];
    float* out = (float*)d_out;

    cudaFuncSetAttribute(kT_tail, cudaFuncAttributeMaxDynamicSharedMemorySize, DYN_BYTES);

    // Fork the capture: kB runs concurrently with kA (independent inputs/outputs).
    // Fresh handles each call (kernel_launch runs ~twice; no device memory involved).
    cudaStream_t s2;
    cudaStreamCreateWithFlags(&s2, cudaStreamNonBlocking);
    cudaEvent_t eFork, eJoin;
    cudaEventCreateWithFlags(&eFork, cudaEventDisableTiming);
    cudaEventCreateWithFlags(&eJoin, cudaEventDisableTiming);

    dim3 g1(9, N_);
    cudaEventRecord(eFork, 0);
    cudaStreamWaitEvent(s2, eFork, 0);
    kB_loc<<<g1, 256, 0, s2>>>(ploc, gloc, glabel, domain_label, dboxes);
    cudaEventRecord(eJoin, s2);

    kA_focal<<<g1, 256>>>(plabel, glabel, domain_label);

    cudaStreamWaitEvent(0, eJoin, 0);
    kT_tail<<<N_, 1024, DYN_BYTES>>>(domain_label, out);
}